// round 1
// baseline (speedup 1.0000x reference)
#include <cuda_runtime.h>
#include <math.h>

#define D     256
#define K     8
#define NBLK  148
#define TPB   512
#define WPB   (TPB / 32)
#define EPSF  1e-12f
#define FULLM 0xffffffffu

// ---- scratch (no allocations allowed; fully overwritten every launch) ----
__device__ float g_part_sums[NBLK * K * D];   // per-block per-cluster sums
__device__ int   g_part_counts[NBLK * K];
__device__ float g_part_loss[NBLK];
__device__ float g_sums[K * D];
__device__ int   g_counts[K];
__device__ float g_protos_new[K * D];

__device__ __forceinline__ float warp_sum(float v) {
    v += __shfl_xor_sync(FULLM, v, 16);
    v += __shfl_xor_sync(FULLM, v, 8);
    v += __shfl_xor_sync(FULLM, v, 4);
    v += __shfl_xor_sync(FULLM, v, 2);
    v += __shfl_xor_sync(FULLM, v, 1);
    return v;
}

// ============================================================================
// Kernel 1: per-row argmax assignment + per-cluster normalized sums (partials)
// One warp per row. Register accumulators avoid atomics entirely.
// ============================================================================
__global__ void __launch_bounds__(TPB, 1)
k_assign(const float* __restrict__ src, const float* __restrict__ protos, int N)
{
    __shared__ float s_protos[K * D];     // 8 KB
    __shared__ float s_tmp[WPB * D];      // 16 KB staging for cross-warp reduce
    __shared__ int   s_icnt[WPB * K];

    const int tid  = threadIdx.x;
    const int lane = tid & 31;
    const int warp = tid >> 5;

    // load prototypes to smem (2048 floats = 512 float4 = TPB)
    ((float4*)s_protos)[tid] = ((const float4*)protos)[tid];
    __syncthreads();

    float acc[K][8];
    int   cnt[K];
#pragma unroll
    for (int k = 0; k < K; k++) {
        cnt[k] = 0;
#pragma unroll
        for (int j = 0; j < 8; j++) acc[k][j] = 0.0f;
    }

    const int gw     = blockIdx.x * WPB + warp;
    const int stride = NBLK * WPB;
    const float4* sp = (const float4*)s_protos;

    for (int row = gw; row < N; row += stride) {
        const float4* rp = (const float4*)(src + (size_t)row * D);
        const float4 a = rp[lane];
        const float4 b = rp[lane + 32];

        float ss = a.x*a.x + a.y*a.y + a.z*a.z + a.w*a.w
                 + b.x*b.x + b.y*b.y + b.z*b.z + b.w*b.w;
        ss = warp_sum(ss);
        const float inv = 1.0f / fmaxf(sqrtf(ss), EPSF);

        float dk[K];
#pragma unroll
        for (int k = 0; k < K; k++) {
            const float4 pa = sp[k * 64 + lane];
            const float4 pb = sp[k * 64 + 32 + lane];
            dk[k] = a.x*pa.x + a.y*pa.y + a.z*pa.z + a.w*pa.w
                  + b.x*pb.x + b.y*pb.y + b.z*pb.z + b.w*pb.w;
        }
#pragma unroll
        for (int s = 16; s >= 1; s >>= 1) {
#pragma unroll
            for (int k = 0; k < K; k++) dk[k] += __shfl_xor_sync(FULLM, dk[k], s);
        }

        float best = dk[0];
        int   bk   = 0;
#pragma unroll
        for (int k = 1; k < K; k++) {
            if (dk[k] > best) { best = dk[k]; bk = k; }   // first-max tiebreak
        }

        // accumulate normalized row into the assigned cluster (select-weighted)
#pragma unroll
        for (int k = 0; k < K; k++) {
            const float w = (bk == k) ? inv : 0.0f;
            acc[k][0] += a.x * w; acc[k][1] += a.y * w;
            acc[k][2] += a.z * w; acc[k][3] += a.w * w;
            acc[k][4] += b.x * w; acc[k][5] += b.y * w;
            acc[k][6] += b.z * w; acc[k][7] += b.w * w;
            cnt[k]    += (bk == k);
        }
    }

    // ---- cross-warp reduce via staged smem (no atomics) ----
    __syncthreads();
#pragma unroll
    for (int k = 0; k < K; k++) {
        float4* t4 = (float4*)(s_tmp + warp * D);
        t4[lane]      = make_float4(acc[k][0], acc[k][1], acc[k][2], acc[k][3]);
        t4[lane + 32] = make_float4(acc[k][4], acc[k][5], acc[k][6], acc[k][7]);
        __syncthreads();
        if (tid < D) {
            float s = 0.0f;
#pragma unroll
            for (int w = 0; w < WPB; w++) s += s_tmp[w * D + tid];
            g_part_sums[(blockIdx.x * K + k) * D + tid] = s;
        }
        __syncthreads();
    }

    if (lane == 0) {
#pragma unroll
        for (int k = 0; k < K; k++) s_icnt[warp * K + k] = cnt[k];
    }
    __syncthreads();
    if (tid < K) {
        int s = 0;
#pragma unroll
        for (int w = 0; w < WPB; w++) s += s_icnt[w * K + tid];
        g_part_counts[blockIdx.x * K + tid] = s;
    }
}

// ============================================================================
// Kernel 2: reduce partials (8 blocks x 256 threads, one thread per element)
// ============================================================================
__global__ void k_reduce()
{
    const int e = blockIdx.x * 256 + threadIdx.x;   // 0..2047
    float s = 0.0f;
#pragma unroll 4
    for (int b = 0; b < NBLK; b++) s += g_part_sums[b * (K * D) + e];
    g_sums[e] = s;

    if (blockIdx.x == 0 && threadIdx.x < K) {
        int c = 0;
#pragma unroll 4
        for (int b = 0; b < NBLK; b++) c += g_part_counts[b * K + threadIdx.x];
        g_counts[threadIdx.x] = c;
    }
}

// ============================================================================
// Kernel 3: prototype EMA update + renormalize (1 block, warp k = cluster k)
// ============================================================================
__global__ void k_update(const float* __restrict__ protos)
{
    const int tid  = threadIdx.x;
    const int lane = tid & 31;
    const int k    = tid >> 5;     // 8 warps = 8 clusters

    const float4* s4 = (const float4*)g_sums;
    float4 s1 = s4[k * 64 + lane];
    float4 s2 = s4[k * 64 + 32 + lane];

    const int   c = g_counts[k];
    const float r = 1.0f / fmaxf((float)c, 1.0f);
    float4 m1 = make_float4(s1.x*r, s1.y*r, s1.z*r, s1.w*r);
    float4 m2 = make_float4(s2.x*r, s2.y*r, s2.z*r, s2.w*r);

    float ss = m1.x*m1.x + m1.y*m1.y + m1.z*m1.z + m1.w*m1.w
             + m2.x*m2.x + m2.y*m2.y + m2.z*m2.z + m2.w*m2.w;
    ss = warp_sum(ss);
    const float inv = 1.0f / fmaxf(sqrtf(ss), EPSF);

    const float4* p4 = (const float4*)protos;
    const float4 p1 = p4[k * 64 + lane];
    const float4 p2 = p4[k * 64 + 32 + lane];

    float4 u1, u2;
    if (c > 0) {
        u1 = make_float4(0.9f*p1.x + 0.1f*m1.x*inv, 0.9f*p1.y + 0.1f*m1.y*inv,
                         0.9f*p1.z + 0.1f*m1.z*inv, 0.9f*p1.w + 0.1f*m1.w*inv);
        u2 = make_float4(0.9f*p2.x + 0.1f*m2.x*inv, 0.9f*p2.y + 0.1f*m2.y*inv,
                         0.9f*p2.z + 0.1f*m2.z*inv, 0.9f*p2.w + 0.1f*m2.w*inv);
    } else {
        u1 = p1; u2 = p2;
    }

    float ss2 = u1.x*u1.x + u1.y*u1.y + u1.z*u1.z + u1.w*u1.w
              + u2.x*u2.x + u2.y*u2.y + u2.z*u2.z + u2.w*u2.w;
    ss2 = warp_sum(ss2);
    const float inv2 = 1.0f / fmaxf(sqrtf(ss2), EPSF);

    float4* o4 = (float4*)g_protos_new;
    o4[k * 64 + lane]      = make_float4(u1.x*inv2, u1.y*inv2, u1.z*inv2, u1.w*inv2);
    o4[k * 64 + 32 + lane] = make_float4(u2.x*inv2, u2.y*inv2, u2.z*inv2, u2.w*inv2);
}

// ============================================================================
// Kernel 4: target loss = sum over rows of (1 - max_k cos(x, proto_k))
// ============================================================================
__global__ void __launch_bounds__(TPB, 1)
k_loss(const float* __restrict__ tgt, int N)
{
    __shared__ float s_protos[K * D];
    __shared__ float s_l[WPB];

    const int tid  = threadIdx.x;
    const int lane = tid & 31;
    const int warp = tid >> 5;

    ((float4*)s_protos)[tid] = ((const float4*)g_protos_new)[tid];
    __syncthreads();

    const int gw     = blockIdx.x * WPB + warp;
    const int stride = NBLK * WPB;
    const float4* sp = (const float4*)s_protos;

    float lsum = 0.0f;
    for (int row = gw; row < N; row += stride) {
        const float4* rp = (const float4*)(tgt + (size_t)row * D);
        const float4 a = rp[lane];
        const float4 b = rp[lane + 32];

        float ss = a.x*a.x + a.y*a.y + a.z*a.z + a.w*a.w
                 + b.x*b.x + b.y*b.y + b.z*b.z + b.w*b.w;
        ss = warp_sum(ss);
        const float inv = 1.0f / fmaxf(sqrtf(ss), EPSF);

        float dk[K];
#pragma unroll
        for (int k = 0; k < K; k++) {
            const float4 pa = sp[k * 64 + lane];
            const float4 pb = sp[k * 64 + 32 + lane];
            dk[k] = a.x*pa.x + a.y*pa.y + a.z*pa.z + a.w*pa.w
                  + b.x*pb.x + b.y*pb.y + b.z*pb.z + b.w*pb.w;
        }
#pragma unroll
        for (int s = 16; s >= 1; s >>= 1) {
#pragma unroll
            for (int k = 0; k < K; k++) dk[k] += __shfl_xor_sync(FULLM, dk[k], s);
        }

        float best = dk[0];
#pragma unroll
        for (int k = 1; k < K; k++) best = fmaxf(best, dk[k]);

        if (lane == 0) lsum += 1.0f - best * inv;
    }

    if (lane == 0) s_l[warp] = lsum;
    __syncthreads();
    if (tid == 0) {
        float s = 0.0f;
#pragma unroll
        for (int w = 0; w < WPB; w++) s += s_l[w];
        g_part_loss[blockIdx.x] = s;
    }
}

// ============================================================================
// Kernel 5: final mean
// ============================================================================
__global__ void k_final(float* __restrict__ out, int Nt)
{
    __shared__ float sw[8];
    const int tid  = threadIdx.x;
    const int lane = tid & 31;
    const int warp = tid >> 5;

    float v = (tid < NBLK) ? g_part_loss[tid] : 0.0f;
    v = warp_sum(v);
    if (lane == 0) sw[warp] = v;
    __syncthreads();
    if (tid == 0) {
        float s = 0.0f;
#pragma unroll
        for (int w = 0; w < 8; w++) s += sw[w];
        out[0] = s / (float)Nt;
    }
}

// ============================================================================
extern "C" void kernel_launch(void* const* d_in, const int* in_sizes, int n_in,
                              void* d_out, int out_size)
{
    const float* src    = (const float*)d_in[0];   // source_feat [Ns, 256]
    const float* tgt    = (const float*)d_in[1];   // target_feat [Nt, 256]
    const float* protos = (const float*)d_in[2];   // prototypes  [8, 256]
    float* out = (float*)d_out;

    const int Ns = in_sizes[0] / D;
    const int Nt = in_sizes[1] / D;

    k_assign<<<NBLK, TPB>>>(src, protos, Ns);
    k_reduce<<<8, 256>>>();
    k_update<<<1, 256>>>(protos);
    k_loss<<<NBLK, TPB>>>(tgt, Nt);
    k_final<<<1, 256>>>(out, Nt);
}

// round 2
// speedup vs baseline: 1.3470x; 1.3470x over previous
#include <cuda_runtime.h>
#include <math.h>

#define D       256
#define K       8
#define EPSF    1e-12f
#define FULLM   0xffffffffu

// k_assign config: 128 threads (4 warps), 4 CTAs/SM
#define A_TPB   128
#define A_WPB   4
#define A_GRID  592          // 4 * 148
// k_loss config: 256 threads (8 warps), 2 CTAs/SM
#define L_TPB   256
#define L_WPB   8
#define L_GRID  296          // 2 * 148
#define RCHUNK  74           // 592 / 8 reduce stage chunking

typedef unsigned long long u64;

// ---- device scratch (no allocations allowed) ----
__device__ float g_part_sums[A_GRID * K * D];   // per-block per-cluster sums
__device__ int   g_part_counts[A_GRID * K];
__device__ float g_mid[8 * K * D];              // stage-2 partials
__device__ float g_part_loss[L_GRID];
__device__ float g_protos_new[K * D];

// ---------------- f32x2 packed helpers ----------------
__device__ __forceinline__ u64 pk2(float lo, float hi) {
    u64 r; asm("mov.b64 %0, {%1, %2};" : "=l"(r) : "f"(lo), "f"(hi)); return r;
}
__device__ __forceinline__ float hadd2(u64 v) {
    float lo, hi; asm("mov.b64 {%0, %1}, %2;" : "=f"(lo), "=f"(hi) : "l"(v));
    return lo + hi;
}
__device__ __forceinline__ u64 mul2(u64 a, u64 b) {
    u64 d; asm("mul.rn.f32x2 %0, %1, %2;" : "=l"(d) : "l"(a), "l"(b)); return d;
}
__device__ __forceinline__ u64 ffma2(u64 a, u64 b, u64 c) {
    u64 d; asm("fma.rn.f32x2 %0, %1, %2, %3;" : "=l"(d) : "l"(a), "l"(b), "l"(c)); return d;
}

__device__ __forceinline__ float warp_sum(float v) {
    v += __shfl_xor_sync(FULLM, v, 16);
    v += __shfl_xor_sync(FULLM, v, 8);
    v += __shfl_xor_sync(FULLM, v, 4);
    v += __shfl_xor_sync(FULLM, v, 2);
    v += __shfl_xor_sync(FULLM, v, 1);
    return v;
}

// Folded 8-value warp reduction: 9 shuffles. On return v0 of lane l holds
// the full 32-lane sum of value index k(l) = (l >> 2) & 7.
__device__ __forceinline__ float fold8(const float* v, int lane) {
    float v0, v1, v2, v3;
    {   // fold bit 4 (8 -> 4 values)
        bool hi = (lane & 16) != 0;
        float k0 = hi ? v[4] : v[0], k1 = hi ? v[5] : v[1];
        float k2 = hi ? v[6] : v[2], k3 = hi ? v[7] : v[3];
        float s0 = hi ? v[0] : v[4], s1 = hi ? v[1] : v[5];
        float s2 = hi ? v[2] : v[6], s3 = hi ? v[3] : v[7];
        v0 = k0 + __shfl_xor_sync(FULLM, s0, 16);
        v1 = k1 + __shfl_xor_sync(FULLM, s1, 16);
        v2 = k2 + __shfl_xor_sync(FULLM, s2, 16);
        v3 = k3 + __shfl_xor_sync(FULLM, s3, 16);
    }
    {   // fold bit 3 (4 -> 2)
        bool hi = (lane & 8) != 0;
        float k0 = hi ? v2 : v0, k1 = hi ? v3 : v1;
        float s0 = hi ? v0 : v2, s1 = hi ? v1 : v3;
        v0 = k0 + __shfl_xor_sync(FULLM, s0, 8);
        v1 = k1 + __shfl_xor_sync(FULLM, s1, 8);
    }
    {   // fold bit 2 (2 -> 1)
        bool hi = (lane & 4) != 0;
        float k0 = hi ? v1 : v0;
        float s0 = hi ? v0 : v1;
        v0 = k0 + __shfl_xor_sync(FULLM, s0, 4);
    }
    // plain sum over bits 1, 0
    v0 += __shfl_xor_sync(FULLM, v0, 2);
    v0 += __shfl_xor_sync(FULLM, v0, 1);
    return v0;
}

// ============================================================================
// Kernel 1: assignment + per-cluster normalized sums (per-block partials)
// ============================================================================
__global__ void __launch_bounds__(A_TPB, 4)
k_assign(const float* __restrict__ src, const float* __restrict__ protos, int N)
{
    __shared__ float s_acc[A_WPB * K * D];   // 32 KB: [warp][k][col]
    __shared__ int   s_icnt[A_WPB * K];

    const int tid  = threadIdx.x;
    const int lane = tid & 31;
    const int warp = tid >> 5;

    // zero accumulators
    for (int e = tid; e < A_WPB * K * D; e += A_TPB) s_acc[e] = 0.0f;

    // prototypes into registers: lane owns its 8-float column slice per k
    const ulonglong2* up = (const ulonglong2*)protos;
    ulonglong2 PA[K], PB[K];
#pragma unroll
    for (int k = 0; k < K; k++) {
        PA[k] = up[k * 64 + lane];
        PB[k] = up[k * 64 + 32 + lane];
    }
    __syncthreads();

    int cnt = 0;   // counts rows assigned to cluster (lane & 7)

    const int gw     = blockIdx.x * A_WPB + warp;
    const int stride = A_GRID * A_WPB;

    for (int row = gw; row < N; row += stride) {
        const ulonglong2* rp = (const ulonglong2*)src + (size_t)row * 64;
        const ulonglong2 A = rp[lane];
        const ulonglong2 B = rp[lane + 32];

        u64 ss2 = mul2(A.x, A.x);
        ss2 = ffma2(A.y, A.y, ss2);
        ss2 = ffma2(B.x, B.x, ss2);
        ss2 = ffma2(B.y, B.y, ss2);

        float v[K];
#pragma unroll
        for (int k = 0; k < K; k++) {
            u64 d = mul2(A.x, PA[k].x);
            d = ffma2(A.y, PA[k].y, d);
            d = ffma2(B.x, PB[k].x, d);
            d = ffma2(B.y, PB[k].y, d);
            v[k] = hadd2(d);
        }

        float ss = warp_sum(hadd2(ss2));
        const float inv = 1.0f / fmaxf(sqrtf(ss), EPSF);

        float dv = fold8(v, lane);
        // argmax with first-max tiebreak (smallest k wins)
        float bv = dv;
        int   bk = (lane >> 2) & 7;
#pragma unroll
        for (int s = 4; s <= 16; s <<= 1) {
            float ov = __shfl_xor_sync(FULLM, bv, s);
            int   ok = __shfl_xor_sync(FULLM, bk, s);
            if (ov > bv || (ov == bv && ok < bk)) { bv = ov; bk = ok; }
        }

        cnt += (bk == (lane & 7));

        const u64 inv2 = pk2(inv, inv);
        ulonglong2* ap = (ulonglong2*)(s_acc + (warp * K + bk) * D) + lane;
        ulonglong2 c0 = ap[0];
        c0.x = ffma2(A.x, inv2, c0.x);
        c0.y = ffma2(A.y, inv2, c0.y);
        ap[0] = c0;
        ulonglong2 c1 = ap[32];
        c1.x = ffma2(B.x, inv2, c1.x);
        c1.y = ffma2(B.y, inv2, c1.y);
        ap[32] = c1;
    }

    // per-warp per-k counts: lane l tracked k = l&7; sum over lanes l^8, l^16
    cnt += __shfl_xor_sync(FULLM, cnt, 8);
    cnt += __shfl_xor_sync(FULLM, cnt, 16);
    if (lane < K) s_icnt[warp * K + lane] = cnt;
    __syncthreads();

    // reduce 4 warps and write block partials
    for (int e = tid; e < K * D; e += A_TPB) {
        float s = s_acc[e] + s_acc[e + K * D] + s_acc[e + 2 * K * D] + s_acc[e + 3 * K * D];
        g_part_sums[blockIdx.x * (K * D) + e] = s;
    }
    if (tid < K) {
        int c = 0;
#pragma unroll
        for (int w = 0; w < A_WPB; w++) c += s_icnt[w * K + tid];
        g_part_counts[blockIdx.x * K + tid] = c;
    }
}

// ============================================================================
// Kernel 2: reduce 592 partial blocks -> 8 mid blocks (coalesced)
// ============================================================================
__global__ void k_reduce1()
{
    const int be = blockIdx.x & 7;       // element chunk
    const int bb = blockIdx.x >> 3;      // block chunk
    const int e  = be * 256 + threadIdx.x;
    float s = 0.0f;
    const int b0 = bb * RCHUNK;
#pragma unroll 8
    for (int b = b0; b < b0 + RCHUNK; b++) s += g_part_sums[b * (K * D) + e];
    g_mid[bb * (K * D) + e] = s;
}

// ============================================================================
// Kernel 3: final reduce + prototype EMA update + renormalize (1 block)
// ============================================================================
__global__ void k_update(const float* __restrict__ protos)
{
    __shared__ float s_sums[K * D];
    __shared__ int   s_cnt[K];

    const int tid  = threadIdx.x;
    const int lane = tid & 31;
    const int warp = tid >> 5;

    for (int e = tid; e < K * D; e += 256) {
        float s = 0.0f;
#pragma unroll
        for (int m = 0; m < 8; m++) s += g_mid[m * (K * D) + e];
        s_sums[e] = s;
    }
    // counts: warp w sums cluster w
    {
        int c = 0;
        for (int b = lane; b < A_GRID; b += 32) c += g_part_counts[b * K + warp];
        c = __reduce_add_sync(FULLM, c);
        if (lane == 0) s_cnt[warp] = c;
    }
    __syncthreads();

    const int k = warp;   // 8 warps = 8 clusters
    const float4* s4 = (const float4*)s_sums;
    float4 s1 = s4[k * 64 + lane];
    float4 s2 = s4[k * 64 + 32 + lane];

    const int   c = s_cnt[k];
    const float r = 1.0f / fmaxf((float)c, 1.0f);
    float4 m1 = make_float4(s1.x*r, s1.y*r, s1.z*r, s1.w*r);
    float4 m2 = make_float4(s2.x*r, s2.y*r, s2.z*r, s2.w*r);

    float ss = m1.x*m1.x + m1.y*m1.y + m1.z*m1.z + m1.w*m1.w
             + m2.x*m2.x + m2.y*m2.y + m2.z*m2.z + m2.w*m2.w;
    ss = warp_sum(ss);
    const float inv = 1.0f / fmaxf(sqrtf(ss), EPSF);

    const float4* p4 = (const float4*)protos;
    const float4 p1 = p4[k * 64 + lane];
    const float4 p2 = p4[k * 64 + 32 + lane];

    float4 u1, u2;
    if (c > 0) {
        u1 = make_float4(0.9f*p1.x + 0.1f*m1.x*inv, 0.9f*p1.y + 0.1f*m1.y*inv,
                         0.9f*p1.z + 0.1f*m1.z*inv, 0.9f*p1.w + 0.1f*m1.w*inv);
        u2 = make_float4(0.9f*p2.x + 0.1f*m2.x*inv, 0.9f*p2.y + 0.1f*m2.y*inv,
                         0.9f*p2.z + 0.1f*m2.z*inv, 0.9f*p2.w + 0.1f*m2.w*inv);
    } else {
        u1 = p1; u2 = p2;
    }

    float ss2 = u1.x*u1.x + u1.y*u1.y + u1.z*u1.z + u1.w*u1.w
              + u2.x*u2.x + u2.y*u2.y + u2.z*u2.z + u2.w*u2.w;
    ss2 = warp_sum(ss2);
    const float inv2 = 1.0f / fmaxf(sqrtf(ss2), EPSF);

    float4* o4 = (float4*)g_protos_new;
    o4[k * 64 + lane]      = make_float4(u1.x*inv2, u1.y*inv2, u1.z*inv2, u1.w*inv2);
    o4[k * 64 + 32 + lane] = make_float4(u2.x*inv2, u2.y*inv2, u2.z*inv2, u2.w*inv2);
}

// ============================================================================
// Kernel 4: target loss partials
// ============================================================================
__global__ void __launch_bounds__(L_TPB, 2)
k_loss(const float* __restrict__ tgt, int N)
{
    __shared__ float s_l[L_WPB];

    const int tid  = threadIdx.x;
    const int lane = tid & 31;
    const int warp = tid >> 5;

    const ulonglong2* up = (const ulonglong2*)g_protos_new;
    ulonglong2 PA[K], PB[K];
#pragma unroll
    for (int k = 0; k < K; k++) {
        PA[k] = up[k * 64 + lane];
        PB[k] = up[k * 64 + 32 + lane];
    }

    const int gw     = blockIdx.x * L_WPB + warp;
    const int stride = L_GRID * L_WPB;

    float lsum = 0.0f;
    for (int row = gw; row < N; row += stride) {
        const ulonglong2* rp = (const ulonglong2*)tgt + (size_t)row * 64;
        const ulonglong2 A = rp[lane];
        const ulonglong2 B = rp[lane + 32];

        u64 ss2 = mul2(A.x, A.x);
        ss2 = ffma2(A.y, A.y, ss2);
        ss2 = ffma2(B.x, B.x, ss2);
        ss2 = ffma2(B.y, B.y, ss2);

        float v[K];
#pragma unroll
        for (int k = 0; k < K; k++) {
            u64 d = mul2(A.x, PA[k].x);
            d = ffma2(A.y, PA[k].y, d);
            d = ffma2(B.x, PB[k].x, d);
            d = ffma2(B.y, PB[k].y, d);
            v[k] = hadd2(d);
        }

        float ss = warp_sum(hadd2(ss2));
        const float inv = 1.0f / fmaxf(sqrtf(ss), EPSF);

        float dv = fold8(v, lane);
        dv = fmaxf(dv, __shfl_xor_sync(FULLM, dv, 4));
        dv = fmaxf(dv, __shfl_xor_sync(FULLM, dv, 8));
        dv = fmaxf(dv, __shfl_xor_sync(FULLM, dv, 16));

        if (lane == 0) lsum += 1.0f - dv * inv;
    }

    if (lane == 0) s_l[warp] = lsum;
    __syncthreads();
    if (tid == 0) {
        float s = 0.0f;
#pragma unroll
        for (int w = 0; w < L_WPB; w++) s += s_l[w];
        g_part_loss[blockIdx.x] = s;
    }
}

// ============================================================================
// Kernel 5: final mean
// ============================================================================
__global__ void k_final(float* __restrict__ out, int Nt)
{
    __shared__ float sw[16];
    const int tid  = threadIdx.x;
    const int lane = tid & 31;
    const int warp = tid >> 5;

    float v = (tid < L_GRID) ? g_part_loss[tid] : 0.0f;
    v = warp_sum(v);
    if (lane == 0) sw[warp] = v;
    __syncthreads();
    if (tid == 0) {
        float s = 0.0f;
#pragma unroll
        for (int w = 0; w < 16; w++) s += sw[w];
        out[0] = s / (float)Nt;
    }
}

// ============================================================================
extern "C" void kernel_launch(void* const* d_in, const int* in_sizes, int n_in,
                              void* d_out, int out_size)
{
    const float* src    = (const float*)d_in[0];
    const float* tgt    = (const float*)d_in[1];
    const float* protos = (const float*)d_in[2];
    float* out = (float*)d_out;

    const int Ns = in_sizes[0] / D;
    const int Nt = in_sizes[1] / D;

    k_assign<<<A_GRID, A_TPB>>>(src, protos, Ns);
    k_reduce1<<<64, 256>>>();
    k_update<<<1, 256>>>(protos);
    k_loss<<<L_GRID, L_TPB>>>(tgt, Nt);
    k_final<<<1, 512>>>(out, Nt);
}

// round 3
// speedup vs baseline: 1.8570x; 1.3786x over previous
#include <cuda_runtime.h>
#include <math.h>

#define D       256
#define K       8
#define FULLM   0xffffffffu

// both big kernels: 128 threads (4 warps), 4 CTAs/SM
#define A_TPB   128
#define A_WPB   4
#define A_GRID  592          // 4 * 148
#define RCHUNK  74           // 592 / 8 reduce-stage chunking

typedef unsigned long long u64;

// ---- device scratch (no allocations allowed) ----
__device__ float g_part_sums[A_GRID * K * D];   // per-block per-cluster sums
__device__ int   g_part_counts[A_GRID * K];
__device__ float g_mid[8 * K * D];              // stage-2 partials
__device__ float g_part_loss[A_GRID];
__device__ float g_protos_new[K * D];

// ---------------- f32x2 packed helpers ----------------
__device__ __forceinline__ u64 pk2(float lo, float hi) {
    u64 r; asm("mov.b64 %0, {%1, %2};" : "=l"(r) : "f"(lo), "f"(hi)); return r;
}
__device__ __forceinline__ float hadd2(u64 v) {
    float lo, hi; asm("mov.b64 {%0, %1}, %2;" : "=f"(lo), "=f"(hi) : "l"(v));
    return lo + hi;
}
__device__ __forceinline__ u64 mul2(u64 a, u64 b) {
    u64 d; asm("mul.rn.f32x2 %0, %1, %2;" : "=l"(d) : "l"(a), "l"(b)); return d;
}
__device__ __forceinline__ u64 ffma2(u64 a, u64 b, u64 c) {
    u64 d; asm("fma.rn.f32x2 %0, %1, %2, %3;" : "=l"(d) : "l"(a), "l"(b), "l"(c)); return d;
}

__device__ __forceinline__ float warp_sum(float v) {
    v += __shfl_xor_sync(FULLM, v, 16);
    v += __shfl_xor_sync(FULLM, v, 8);
    v += __shfl_xor_sync(FULLM, v, 4);
    v += __shfl_xor_sync(FULLM, v, 2);
    v += __shfl_xor_sync(FULLM, v, 1);
    return v;
}

// Folded 8-value warp reduction: 9 shuffles. On return, lane l holds the
// full 32-lane sum of value index k(l) = (l >> 2) & 7.
__device__ __forceinline__ float fold8(const float* v, int lane) {
    float v0, v1, v2, v3;
    {
        bool hi = (lane & 16) != 0;
        float k0 = hi ? v[4] : v[0], k1 = hi ? v[5] : v[1];
        float k2 = hi ? v[6] : v[2], k3 = hi ? v[7] : v[3];
        float s0 = hi ? v[0] : v[4], s1 = hi ? v[1] : v[5];
        float s2 = hi ? v[2] : v[6], s3 = hi ? v[3] : v[7];
        v0 = k0 + __shfl_xor_sync(FULLM, s0, 16);
        v1 = k1 + __shfl_xor_sync(FULLM, s1, 16);
        v2 = k2 + __shfl_xor_sync(FULLM, s2, 16);
        v3 = k3 + __shfl_xor_sync(FULLM, s3, 16);
    }
    {
        bool hi = (lane & 8) != 0;
        float k0 = hi ? v2 : v0, k1 = hi ? v3 : v1;
        float s0 = hi ? v0 : v2, s1 = hi ? v1 : v3;
        v0 = k0 + __shfl_xor_sync(FULLM, s0, 8);
        v1 = k1 + __shfl_xor_sync(FULLM, s1, 8);
    }
    {
        bool hi = (lane & 4) != 0;
        float k0 = hi ? v1 : v0;
        float s0 = hi ? v0 : v1;
        v0 = k0 + __shfl_xor_sync(FULLM, s0, 4);
    }
    v0 += __shfl_xor_sync(FULLM, v0, 2);
    v0 += __shfl_xor_sync(FULLM, v0, 1);
    return v0;
}

// ============================================================================
// Kernel 1: assignment + per-cluster normalized sums (per-block partials)
// ============================================================================
__global__ void __launch_bounds__(A_TPB, 4)
k_assign(const float* __restrict__ src, const float* __restrict__ protos, int N)
{
    __shared__ float s_acc[A_WPB * K * D];   // 32 KB: [warp][k][col]
    __shared__ int   s_icnt[A_WPB * K];

    const int tid  = threadIdx.x;
    const int lane = tid & 31;
    const int warp = tid >> 5;

    for (int e = tid; e < A_WPB * K * D; e += A_TPB) s_acc[e] = 0.0f;

    // prototypes into registers: lane owns its 8-float column slice per k
    const ulonglong2* up = (const ulonglong2*)protos;
    ulonglong2 PA[K], PB[K];
#pragma unroll
    for (int k = 0; k < K; k++) {
        PA[k] = up[k * 64 + lane];
        PB[k] = up[k * 64 + 32 + lane];
    }
    __syncthreads();

    int cnt = 0;   // rows assigned to cluster (lane & 7)

    const int gw     = blockIdx.x * A_WPB + warp;
    const int stride = A_GRID * A_WPB;

    int row = gw;
    ulonglong2 A, B;
    if (row < N) {
        const ulonglong2* rp = (const ulonglong2*)src + (size_t)row * 64;
        A = rp[lane];
        B = rp[lane + 32];
    }

    while (row < N) {
        const int nrow = row + stride;
        ulonglong2 An = A, Bn = B;
        if (nrow < N) {
            const ulonglong2* np = (const ulonglong2*)src + (size_t)nrow * 64;
            An = np[lane];
            Bn = np[lane + 32];
        }

        u64 ss2 = mul2(A.x, A.x);
        ss2 = ffma2(A.y, A.y, ss2);
        ss2 = ffma2(B.x, B.x, ss2);
        ss2 = ffma2(B.y, B.y, ss2);

        float v[K];
#pragma unroll
        for (int k = 0; k < K; k++) {
            u64 d = mul2(A.x, PA[k].x);
            d = ffma2(A.y, PA[k].y, d);
            d = ffma2(B.x, PB[k].x, d);
            d = ffma2(B.y, PB[k].y, d);
            v[k] = hadd2(d);
        }

        float ss = warp_sum(hadd2(ss2));
        const float inv = rsqrtf(fmaxf(ss, 1e-24f));

        float dv = fold8(v, lane);
        // argmax with first-max tiebreak (smallest k wins)
        float bv = dv;
        int   bk = (lane >> 2) & 7;
#pragma unroll
        for (int s = 4; s <= 16; s <<= 1) {
            float ov = __shfl_xor_sync(FULLM, bv, s);
            int   ok = __shfl_xor_sync(FULLM, bk, s);
            if (ov > bv || (ov == bv && ok < bk)) { bv = ov; bk = ok; }
        }

        cnt += (bk == (lane & 7));

        const u64 inv2 = pk2(inv, inv);
        ulonglong2* ap = (ulonglong2*)(s_acc + (warp * K + bk) * D) + lane;
        ulonglong2 c0 = ap[0];
        c0.x = ffma2(A.x, inv2, c0.x);
        c0.y = ffma2(A.y, inv2, c0.y);
        ap[0] = c0;
        ulonglong2 c1 = ap[32];
        c1.x = ffma2(B.x, inv2, c1.x);
        c1.y = ffma2(B.y, inv2, c1.y);
        ap[32] = c1;

        A = An; B = Bn;
        row = nrow;
    }

    cnt += __shfl_xor_sync(FULLM, cnt, 8);
    cnt += __shfl_xor_sync(FULLM, cnt, 16);
    if (lane < K) s_icnt[warp * K + lane] = cnt;
    __syncthreads();

    for (int e = tid; e < K * D; e += A_TPB) {
        float s = s_acc[e] + s_acc[e + K * D] + s_acc[e + 2 * K * D] + s_acc[e + 3 * K * D];
        g_part_sums[blockIdx.x * (K * D) + e] = s;
    }
    if (tid < K) {
        int c = 0;
#pragma unroll
        for (int w = 0; w < A_WPB; w++) c += s_icnt[w * K + tid];
        g_part_counts[blockIdx.x * K + tid] = c;
    }
}

// ============================================================================
// Kernel 2: reduce 592 partial blocks -> 8 mid blocks (coalesced)
// ============================================================================
__global__ void k_reduce1()
{
    const int be = blockIdx.x & 7;
    const int bb = blockIdx.x >> 3;
    const int e  = be * 256 + threadIdx.x;
    float s = 0.0f;
    const int b0 = bb * RCHUNK;
#pragma unroll 8
    for (int b = b0; b < b0 + RCHUNK; b++) s += g_part_sums[b * (K * D) + e];
    g_mid[bb * (K * D) + e] = s;
}

// ============================================================================
// Kernel 3: final reduce + prototype EMA update + renormalize (1 block)
// ============================================================================
__global__ void k_update(const float* __restrict__ protos)
{
    __shared__ float s_sums[K * D];
    __shared__ int   s_cnt[K];

    const int tid  = threadIdx.x;
    const int lane = tid & 31;
    const int warp = tid >> 5;

    for (int e = tid; e < K * D; e += 256) {
        float s = 0.0f;
#pragma unroll
        for (int m = 0; m < 8; m++) s += g_mid[m * (K * D) + e];
        s_sums[e] = s;
    }
    {
        int c = 0;
        for (int b = lane; b < A_GRID; b += 32) c += g_part_counts[b * K + warp];
        c = __reduce_add_sync(FULLM, c);
        if (lane == 0) s_cnt[warp] = c;
    }
    __syncthreads();

    const int k = warp;   // 8 warps = 8 clusters
    const float4* s4 = (const float4*)s_sums;
    float4 s1 = s4[k * 64 + lane];
    float4 s2 = s4[k * 64 + 32 + lane];

    const int   c = s_cnt[k];
    const float r = 1.0f / fmaxf((float)c, 1.0f);
    float4 m1 = make_float4(s1.x*r, s1.y*r, s1.z*r, s1.w*r);
    float4 m2 = make_float4(s2.x*r, s2.y*r, s2.z*r, s2.w*r);

    float ss = m1.x*m1.x + m1.y*m1.y + m1.z*m1.z + m1.w*m1.w
             + m2.x*m2.x + m2.y*m2.y + m2.z*m2.z + m2.w*m2.w;
    ss = warp_sum(ss);
    const float inv = 1.0f / fmaxf(sqrtf(ss), 1e-12f);

    const float4* p4 = (const float4*)protos;
    const float4 p1 = p4[k * 64 + lane];
    const float4 p2 = p4[k * 64 + 32 + lane];

    float4 u1, u2;
    if (c > 0) {
        u1 = make_float4(0.9f*p1.x + 0.1f*m1.x*inv, 0.9f*p1.y + 0.1f*m1.y*inv,
                         0.9f*p1.z + 0.1f*m1.z*inv, 0.9f*p1.w + 0.1f*m1.w*inv);
        u2 = make_float4(0.9f*p2.x + 0.1f*m2.x*inv, 0.9f*p2.y + 0.1f*m2.y*inv,
                         0.9f*p2.z + 0.1f*m2.z*inv, 0.9f*p2.w + 0.1f*m2.w*inv);
    } else {
        u1 = p1; u2 = p2;
    }

    float ss2 = u1.x*u1.x + u1.y*u1.y + u1.z*u1.z + u1.w*u1.w
              + u2.x*u2.x + u2.y*u2.y + u2.z*u2.z + u2.w*u2.w;
    ss2 = warp_sum(ss2);
    const float inv2 = 1.0f / fmaxf(sqrtf(ss2), 1e-12f);

    float4* o4 = (float4*)g_protos_new;
    o4[k * 64 + lane]      = make_float4(u1.x*inv2, u1.y*inv2, u1.z*inv2, u1.w*inv2);
    o4[k * 64 + 32 + lane] = make_float4(u2.x*inv2, u2.y*inv2, u2.z*inv2, u2.w*inv2);
}

// ============================================================================
// Kernel 4: target loss partials — accumulates sum of max cos-sim
// ============================================================================
__global__ void __launch_bounds__(A_TPB, 4)
k_loss(const float* __restrict__ tgt, int N)
{
    __shared__ float s_l[A_WPB];

    const int tid  = threadIdx.x;
    const int lane = tid & 31;
    const int warp = tid >> 5;

    const ulonglong2* up = (const ulonglong2*)g_protos_new;
    ulonglong2 PA[K], PB[K];
#pragma unroll
    for (int k = 0; k < K; k++) {
        PA[k] = up[k * 64 + lane];
        PB[k] = up[k * 64 + 32 + lane];
    }

    const int gw     = blockIdx.x * A_WPB + warp;
    const int stride = A_GRID * A_WPB;

    float lsum = 0.0f;

    int row = gw;
    ulonglong2 A, B;
    if (row < N) {
        const ulonglong2* rp = (const ulonglong2*)tgt + (size_t)row * 64;
        A = rp[lane];
        B = rp[lane + 32];
    }

    while (row < N) {
        const int nrow = row + stride;
        ulonglong2 An = A, Bn = B;
        if (nrow < N) {
            const ulonglong2* np = (const ulonglong2*)tgt + (size_t)nrow * 64;
            An = np[lane];
            Bn = np[lane + 32];
        }

        u64 ss2 = mul2(A.x, A.x);
        ss2 = ffma2(A.y, A.y, ss2);
        ss2 = ffma2(B.x, B.x, ss2);
        ss2 = ffma2(B.y, B.y, ss2);

        float v[K];
#pragma unroll
        for (int k = 0; k < K; k++) {
            u64 d = mul2(A.x, PA[k].x);
            d = ffma2(A.y, PA[k].y, d);
            d = ffma2(B.x, PB[k].x, d);
            d = ffma2(B.y, PB[k].y, d);
            v[k] = hadd2(d);
        }

        float ss = warp_sum(hadd2(ss2));
        const float inv = rsqrtf(fmaxf(ss, 1e-24f));

        float dv = fold8(v, lane);
        dv = fmaxf(dv, __shfl_xor_sync(FULLM, dv, 4));
        dv = fmaxf(dv, __shfl_xor_sync(FULLM, dv, 8));
        dv = fmaxf(dv, __shfl_xor_sync(FULLM, dv, 16));

        if (lane == 0) lsum += dv * inv;   // (1 - .) hoisted to k_final

        A = An; B = Bn;
        row = nrow;
    }

    if (lane == 0) s_l[warp] = lsum;
    __syncthreads();
    if (tid == 0) {
        float s = 0.0f;
#pragma unroll
        for (int w = 0; w < A_WPB; w++) s += s_l[w];
        g_part_loss[blockIdx.x] = s;
    }
}

// ============================================================================
// Kernel 5: final mean:  out = 1 - (sum of max cos) / Nt
// ============================================================================
__global__ void k_final(float* __restrict__ out, int Nt)
{
    __shared__ float sw[16];
    const int tid  = threadIdx.x;
    const int lane = tid & 31;
    const int warp = tid >> 5;

    float v = (tid < A_GRID) ? g_part_loss[tid] : 0.0f;
    if (tid + 512 < A_GRID) v += g_part_loss[tid + 512];
    v = warp_sum(v);
    if (lane == 0) sw[warp] = v;
    __syncthreads();
    if (tid == 0) {
        float s = 0.0f;
#pragma unroll
        for (int w = 0; w < 16; w++) s += sw[w];
        out[0] = 1.0f - s / (float)Nt;
    }
}

// ============================================================================
extern "C" void kernel_launch(void* const* d_in, const int* in_sizes, int n_in,
                              void* d_out, int out_size)
{
    const float* src    = (const float*)d_in[0];
    const float* tgt    = (const float*)d_in[1];
    const float* protos = (const float*)d_in[2];
    float* out = (float*)d_out;

    const int Ns = in_sizes[0] / D;
    const int Nt = in_sizes[1] / D;

    k_assign<<<A_GRID, A_TPB>>>(src, protos, Ns);
    k_reduce1<<<64, 256>>>();
    k_update<<<1, 256>>>(protos);
    k_loss<<<A_GRID, A_TPB>>>(tgt, Nt);
    k_final<<<1, 512>>>(out, Nt);
}

// round 5
// speedup vs baseline: 2.1961x; 1.1826x over previous
#include <cuda_runtime.h>
#include <math.h>

#define D       256
#define K       8
#define FULLM   0xffffffffu

// both big kernels: 128 threads (4 warps), 3 CTAs/SM
#define A_TPB   128
#define A_WPB   4
#define A_GRID  444          // 3 * 148
#define NWARPS  (A_GRID * A_WPB)

typedef unsigned long long u64;

// ---- device scratch (no allocations allowed) ----
__device__ float g_part_sums[A_GRID * K * D];   // per-block per-cluster sums
__device__ int   g_part_counts[A_GRID * K];
__device__ float g_mid[8 * K * D];              // stage-2 partials
__device__ float g_part_loss[A_GRID];
__device__ float g_protos_new[K * D];

// ---------------- f32x2 packed helpers ----------------
__device__ __forceinline__ u64 pk2(float lo, float hi) {
    u64 r; asm("mov.b64 %0, {%1, %2};" : "=l"(r) : "f"(lo), "f"(hi)); return r;
}
__device__ __forceinline__ float hadd2(u64 v) {
    float lo, hi; asm("mov.b64 {%0, %1}, %2;" : "=f"(lo), "=f"(hi) : "l"(v));
    return lo + hi;
}
__device__ __forceinline__ u64 mul2(u64 a, u64 b) {
    u64 d; asm("mul.rn.f32x2 %0, %1, %2;" : "=l"(d) : "l"(a), "l"(b)); return d;
}
__device__ __forceinline__ u64 ffma2(u64 a, u64 b, u64 c) {
    u64 d; asm("fma.rn.f32x2 %0, %1, %2, %3;" : "=l"(d) : "l"(a), "l"(b), "l"(c)); return d;
}

__device__ __forceinline__ float warp_sum(float v) {
    v += __shfl_xor_sync(FULLM, v, 16);
    v += __shfl_xor_sync(FULLM, v, 8);
    v += __shfl_xor_sync(FULLM, v, 4);
    v += __shfl_xor_sync(FULLM, v, 2);
    v += __shfl_xor_sync(FULLM, v, 1);
    return v;
}

// Folded 8-value warp reduction: 9 shuffles. On return, lane l holds the
// full 32-lane sum of value index k(l) = (l >> 2) & 7.
__device__ __forceinline__ float fold8(const float* v, int lane) {
    float v0, v1, v2, v3;
    {
        bool hi = (lane & 16) != 0;
        float k0 = hi ? v[4] : v[0], k1 = hi ? v[5] : v[1];
        float k2 = hi ? v[6] : v[2], k3 = hi ? v[7] : v[3];
        float s0 = hi ? v[0] : v[4], s1 = hi ? v[1] : v[5];
        float s2 = hi ? v[2] : v[6], s3 = hi ? v[3] : v[7];
        v0 = k0 + __shfl_xor_sync(FULLM, s0, 16);
        v1 = k1 + __shfl_xor_sync(FULLM, s1, 16);
        v2 = k2 + __shfl_xor_sync(FULLM, s2, 16);
        v3 = k3 + __shfl_xor_sync(FULLM, s3, 16);
    }
    {
        bool hi = (lane & 8) != 0;
        float k0 = hi ? v2 : v0, k1 = hi ? v3 : v1;
        float s0 = hi ? v0 : v2, s1 = hi ? v1 : v3;
        v0 = k0 + __shfl_xor_sync(FULLM, s0, 8);
        v1 = k1 + __shfl_xor_sync(FULLM, s1, 8);
    }
    {
        bool hi = (lane & 4) != 0;
        float k0 = hi ? v1 : v0;
        float s0 = hi ? v0 : v1;
        v0 = k0 + __shfl_xor_sync(FULLM, s0, 4);
    }
    v0 += __shfl_xor_sync(FULLM, v0, 2);
    v0 += __shfl_xor_sync(FULLM, v0, 1);
    return v0;
}

// per-row core: packed dots vs 8 prototypes + self norm (no reductions)
__device__ __forceinline__ void dots8(const ulonglong2& A, const ulonglong2& B,
                                      const ulonglong2* PA, const ulonglong2* PB,
                                      float* v, float& ssout)
{
    u64 ss2 = mul2(A.x, A.x);
    ss2 = ffma2(A.y, A.y, ss2);
    ss2 = ffma2(B.x, B.x, ss2);
    ss2 = ffma2(B.y, B.y, ss2);
#pragma unroll
    for (int k = 0; k < K; k++) {
        u64 d = mul2(A.x, PA[k].x);
        d = ffma2(A.y, PA[k].y, d);
        d = ffma2(B.x, PB[k].x, d);
        d = ffma2(B.y, PB[k].y, d);
        v[k] = hadd2(d);
    }
    ssout = hadd2(ss2);
}

// broadcast argmax (first-max tiebreak) given fold8 output dv (lane holds k=(lane>>2)&7)
__device__ __forceinline__ int argmax8(float dv, int lane)
{
    float bv = dv;
    int   bk = (lane >> 2) & 7;
#pragma unroll
    for (int s = 4; s <= 16; s <<= 1) {
        float ov = __shfl_xor_sync(FULLM, bv, s);
        int   ok = __shfl_xor_sync(FULLM, bk, s);
        if (ov > bv || (ov == bv && ok < bk)) { bv = ov; bk = ok; }
    }
    return bk;
}

// ============================================================================
// Kernel 1: assignment + per-cluster normalized sums (per-block partials)
// ============================================================================
__global__ void __launch_bounds__(A_TPB, 3)
k_assign(const float* __restrict__ src, const float* __restrict__ protos, int N)
{
    __shared__ float s_acc[A_WPB * K * D];   // 32 KB: [warp][k][col]
    __shared__ int   s_icnt[A_WPB * K];

    const int tid  = threadIdx.x;
    const int lane = tid & 31;
    const int warp = tid >> 5;

    for (int e = tid; e < A_WPB * K * D; e += A_TPB) s_acc[e] = 0.0f;

    const ulonglong2* up = (const ulonglong2*)protos;
    ulonglong2 PA[K], PB[K];
#pragma unroll
    for (int k = 0; k < K; k++) {
        PA[k] = up[k * 64 + lane];
        PB[k] = up[k * 64 + 32 + lane];
    }
    __syncthreads();

    int cnt = 0;   // rows assigned to cluster (lane & 7)

    const int gw      = blockIdx.x * A_WPB + warp;
    const int Npair   = N & ~1;
    const int stride2 = NWARPS * 2;

    int base = gw * 2;
    ulonglong2 A0, B0, A1, B1;
    if (base < Npair) {
        const ulonglong2* rp = (const ulonglong2*)src + (size_t)base * 64;
        A0 = rp[lane];        B0 = rp[lane + 32];
        A1 = rp[64 + lane];   B1 = rp[64 + lane + 32];
    }

    while (base < Npair) {
        const int nbase = base + stride2;
        ulonglong2 An0 = A0, Bn0 = B0, An1 = A1, Bn1 = B1;
        if (nbase < Npair) {
            const ulonglong2* np = (const ulonglong2*)src + (size_t)nbase * 64;
            An0 = np[lane];        Bn0 = np[lane + 32];
            An1 = np[64 + lane];   Bn1 = np[64 + lane + 32];
        }

        float v0[K], v1[K], ssa, ssb;
        dots8(A0, B0, PA, PB, v0, ssa);
        dots8(A1, B1, PA, PB, v1, ssb);

        // two independent reduction chains — scoreboard interleaves them
        float dv0 = fold8(v0, lane);
        float dv1 = fold8(v1, lane);
        float ss0 = warp_sum(ssa);
        float ss1 = warp_sum(ssb);

        const float inv0 = rsqrtf(fmaxf(ss0, 1e-24f));
        const float inv1 = rsqrtf(fmaxf(ss1, 1e-24f));

        const int bk0 = argmax8(dv0, lane);
        const int bk1 = argmax8(dv1, lane);

        cnt += (bk0 == (lane & 7)) + (bk1 == (lane & 7));

        {
            const u64 iv = pk2(inv0, inv0);
            ulonglong2* ap = (ulonglong2*)(s_acc + (warp * K + bk0) * D) + lane;
            ulonglong2 c0 = ap[0];
            c0.x = ffma2(A0.x, iv, c0.x);
            c0.y = ffma2(A0.y, iv, c0.y);
            ap[0] = c0;
            ulonglong2 c1 = ap[32];
            c1.x = ffma2(B0.x, iv, c1.x);
            c1.y = ffma2(B0.y, iv, c1.y);
            ap[32] = c1;
        }
        {
            const u64 iv = pk2(inv1, inv1);
            ulonglong2* ap = (ulonglong2*)(s_acc + (warp * K + bk1) * D) + lane;
            ulonglong2 c0 = ap[0];
            c0.x = ffma2(A1.x, iv, c0.x);
            c0.y = ffma2(A1.y, iv, c0.y);
            ap[0] = c0;
            ulonglong2 c1 = ap[32];
            c1.x = ffma2(B1.x, iv, c1.x);
            c1.y = ffma2(B1.y, iv, c1.y);
            ap[32] = c1;
        }

        A0 = An0; B0 = Bn0; A1 = An1; B1 = Bn1;
        base = nbase;
    }

    // odd tail row (only if N is odd)
    if ((N & 1) && gw == 0) {
        const int row = N - 1;
        const ulonglong2* rp = (const ulonglong2*)src + (size_t)row * 64;
        ulonglong2 A = rp[lane], B = rp[lane + 32];
        float v[K], ssp;
        dots8(A, B, PA, PB, v, ssp);
        float dv = fold8(v, lane);
        float ss = warp_sum(ssp);
        const float inv = rsqrtf(fmaxf(ss, 1e-24f));
        const int bk = argmax8(dv, lane);
        cnt += (bk == (lane & 7));
        const u64 iv = pk2(inv, inv);
        ulonglong2* ap = (ulonglong2*)(s_acc + (warp * K + bk) * D) + lane;
        ulonglong2 c0 = ap[0];
        c0.x = ffma2(A.x, iv, c0.x);
        c0.y = ffma2(A.y, iv, c0.y);
        ap[0] = c0;
        ulonglong2 c1 = ap[32];
        c1.x = ffma2(B.x, iv, c1.x);
        c1.y = ffma2(B.y, iv, c1.y);
        ap[32] = c1;
    }

    cnt += __shfl_xor_sync(FULLM, cnt, 8);
    cnt += __shfl_xor_sync(FULLM, cnt, 16);
    if (lane < K) s_icnt[warp * K + lane] = cnt;
    __syncthreads();

    for (int e = tid; e < K * D; e += A_TPB) {
        float s = s_acc[e] + s_acc[e + K * D] + s_acc[e + 2 * K * D] + s_acc[e + 3 * K * D];
        g_part_sums[blockIdx.x * (K * D) + e] = s;
    }
    if (tid < K) {
        int c = 0;
#pragma unroll
        for (int w = 0; w < A_WPB; w++) c += s_icnt[w * K + tid];
        g_part_counts[blockIdx.x * K + tid] = c;
    }
}

// ============================================================================
// Kernel 2: reduce 444 partial blocks -> 8 mid blocks (coalesced)
// ============================================================================
#define RCHUNK  56   // ceil(444 / 8)
__global__ void k_reduce1()
{
    const int be = blockIdx.x & 7;
    const int bb = blockIdx.x >> 3;
    const int e  = be * 256 + threadIdx.x;
    float s = 0.0f;
    const int b0 = bb * RCHUNK;
    const int b1 = min(b0 + RCHUNK, A_GRID);
    for (int b = b0; b < b1; b++) s += g_part_sums[b * (K * D) + e];
    g_mid[bb * (K * D) + e] = s;
}

// ============================================================================
// Kernel 3: final reduce + prototype EMA update + renormalize (1 block)
// ============================================================================
__global__ void k_update(const float* __restrict__ protos)
{
    __shared__ float s_sums[K * D];
    __shared__ int   s_cnt[K];

    const int tid  = threadIdx.x;
    const int lane = tid & 31;
    const int warp = tid >> 5;

    for (int e = tid; e < K * D; e += 256) {
        float s = 0.0f;
#pragma unroll
        for (int m = 0; m < 8; m++) s += g_mid[m * (K * D) + e];
        s_sums[e] = s;
    }
    {
        int c = 0;
        for (int b = lane; b < A_GRID; b += 32) c += g_part_counts[b * K + warp];
        c = __reduce_add_sync(FULLM, c);
        if (lane == 0) s_cnt[warp] = c;
    }
    __syncthreads();

    const int k = warp;   // 8 warps = 8 clusters
    const float4* s4 = (const float4*)s_sums;
    float4 s1 = s4[k * 64 + lane];
    float4 s2 = s4[k * 64 + 32 + lane];

    const int   c = s_cnt[k];
    const float r = 1.0f / fmaxf((float)c, 1.0f);
    float4 m1 = make_float4(s1.x*r, s1.y*r, s1.z*r, s1.w*r);
    float4 m2 = make_float4(s2.x*r, s2.y*r, s2.z*r, s2.w*r);

    float ss = m1.x*m1.x + m1.y*m1.y + m1.z*m1.z + m1.w*m1.w
             + m2.x*m2.x + m2.y*m2.y + m2.z*m2.z + m2.w*m2.w;
    ss = warp_sum(ss);
    const float inv = 1.0f / fmaxf(sqrtf(ss), 1e-12f);

    const float4* p4 = (const float4*)protos;
    const float4 p1 = p4[k * 64 + lane];
    const float4 p2 = p4[k * 64 + 32 + lane];

    float4 u1, u2;
    if (c > 0) {
        u1 = make_float4(0.9f*p1.x + 0.1f*m1.x*inv, 0.9f*p1.y + 0.1f*m1.y*inv,
                         0.9f*p1.z + 0.1f*m1.z*inv, 0.9f*p1.w + 0.1f*m1.w*inv);
        u2 = make_float4(0.9f*p2.x + 0.1f*m2.x*inv, 0.9f*p2.y + 0.1f*m2.y*inv,
                         0.9f*p2.z + 0.1f*m2.z*inv, 0.9f*p2.w + 0.1f*m2.w*inv);
    } else {
        u1 = p1; u2 = p2;
    }

    float ss2 = u1.x*u1.x + u1.y*u1.y + u1.z*u1.z + u1.w*u1.w
              + u2.x*u2.x + u2.y*u2.y + u2.z*u2.z + u2.w*u2.w;
    ss2 = warp_sum(ss2);
    const float inv2 = 1.0f / fmaxf(sqrtf(ss2), 1e-12f);

    float4* o4 = (float4*)g_protos_new;
    o4[k * 64 + lane]      = make_float4(u1.x*inv2, u1.y*inv2, u1.z*inv2, u1.w*inv2);
    o4[k * 64 + 32 + lane] = make_float4(u2.x*inv2, u2.y*inv2, u2.z*inv2, u2.w*inv2);
}

// ============================================================================
// Kernel 4: target loss partials — accumulates sum of max cos-sim
// ============================================================================
__global__ void __launch_bounds__(A_TPB, 3)
k_loss(const float* __restrict__ tgt, int N)
{
    __shared__ float s_l[A_WPB];

    const int tid  = threadIdx.x;
    const int lane = tid & 31;
    const int warp = tid >> 5;

    const ulonglong2* up = (const ulonglong2*)g_protos_new;
    ulonglong2 PA[K], PB[K];
#pragma unroll
    for (int k = 0; k < K; k++) {
        PA[k] = up[k * 64 + lane];
        PB[k] = up[k * 64 + 32 + lane];
    }

    const int gw      = blockIdx.x * A_WPB + warp;
    const int Npair   = N & ~1;
    const int stride2 = NWARPS * 2;

    float lsum = 0.0f;

    int base = gw * 2;
    ulonglong2 A0, B0, A1, B1;
    if (base < Npair) {
        const ulonglong2* rp = (const ulonglong2*)tgt + (size_t)base * 64;
        A0 = rp[lane];        B0 = rp[lane + 32];
        A1 = rp[64 + lane];   B1 = rp[64 + lane + 32];
    }

    while (base < Npair) {
        const int nbase = base + stride2;
        ulonglong2 An0 = A0, Bn0 = B0, An1 = A1, Bn1 = B1;
        if (nbase < Npair) {
            const ulonglong2* np = (const ulonglong2*)tgt + (size_t)nbase * 64;
            An0 = np[lane];        Bn0 = np[lane + 32];
            An1 = np[64 + lane];   Bn1 = np[64 + lane + 32];
        }

        float v0[K], v1[K], ssa, ssb;
        dots8(A0, B0, PA, PB, v0, ssa);
        dots8(A1, B1, PA, PB, v1, ssb);

        float dv0 = fold8(v0, lane);
        float dv1 = fold8(v1, lane);
        float ss0 = warp_sum(ssa);
        float ss1 = warp_sum(ssb);

        dv0 = fmaxf(dv0, __shfl_xor_sync(FULLM, dv0, 4));
        dv1 = fmaxf(dv1, __shfl_xor_sync(FULLM, dv1, 4));
        dv0 = fmaxf(dv0, __shfl_xor_sync(FULLM, dv0, 8));
        dv1 = fmaxf(dv1, __shfl_xor_sync(FULLM, dv1, 8));
        dv0 = fmaxf(dv0, __shfl_xor_sync(FULLM, dv0, 16));
        dv1 = fmaxf(dv1, __shfl_xor_sync(FULLM, dv1, 16));

        if (lane == 0) {
            lsum += dv0 * rsqrtf(fmaxf(ss0, 1e-24f));
            lsum += dv1 * rsqrtf(fmaxf(ss1, 1e-24f));
        }

        A0 = An0; B0 = Bn0; A1 = An1; B1 = Bn1;
        base = nbase;
    }

    if ((N & 1) && gw == 0) {
        const int row = N - 1;
        const ulonglong2* rp = (const ulonglong2*)tgt + (size_t)row * 64;
        ulonglong2 A = rp[lane], B = rp[lane + 32];
        float v[K], ssp;
        dots8(A, B, PA, PB, v, ssp);
        float dv = fold8(v, lane);
        float ss = warp_sum(ssp);
        dv = fmaxf(dv, __shfl_xor_sync(FULLM, dv, 4));
        dv = fmaxf(dv, __shfl_xor_sync(FULLM, dv, 8));
        dv = fmaxf(dv, __shfl_xor_sync(FULLM, dv, 16));
        if (lane == 0) lsum += dv * rsqrtf(fmaxf(ss, 1e-24f));
    }

    if (lane == 0) s_l[warp] = lsum;
    __syncthreads();
    if (tid == 0) {
        float s = 0.0f;
#pragma unroll
        for (int w = 0; w < A_WPB; w++) s += s_l[w];
        g_part_loss[blockIdx.x] = s;
    }
}

// ============================================================================
// Kernel 5: final mean:  out = 1 - (sum of max cos) / Nt
// ============================================================================
__global__ void k_final(float* __restrict__ out, int Nt)
{
    __shared__ float sw[16];
    const int tid  = threadIdx.x;
    const int lane = tid & 31;
    const int warp = tid >> 5;

    float v = (tid < A_GRID) ? g_part_loss[tid] : 0.0f;
    v = warp_sum(v);
    if (lane == 0) sw[warp] = v;
    __syncthreads();
    if (tid == 0) {
        float s = 0.0f;
#pragma unroll
        for (int w = 0; w < 16; w++) s += sw[w];
        out[0] = 1.0f - s / (float)Nt;
    }
}

// ============================================================================
extern "C" void kernel_launch(void* const* d_in, const int* in_sizes, int n_in,
                              void* d_out, int out_size)
{
    const float* src    = (const float*)d_in[0];
    const float* tgt    = (const float*)d_in[1];
    const float* protos = (const float*)d_in[2];
    float* out = (float*)d_out;

    const int Ns = in_sizes[0] / D;
    const int Nt = in_sizes[1] / D;

    k_assign<<<A_GRID, A_TPB>>>(src, protos, Ns);
    k_reduce1<<<64, 256>>>();
    k_update<<<1, 256>>>(protos);
    k_loss<<<A_GRID, A_TPB>>>(tgt, Nt);
    k_final<<<1, 512>>>(out, Nt);
}